// round 3
// baseline (speedup 1.0000x reference)
#include <cuda_runtime.h>

#define BB   64
#define TT   512
#define DD   256
#define HH   256
#define G4   (4*HH)
#define NBLK 128     // persistent blocks; each owns 2 hidden units
#define NTHR 256     // 64 batches x 4 col-groups

// h after each step: g_h[t][b][unit]  (33.5 MB static device buffer)
__device__ float g_h[TT][BB][HH];
// per-step arrival counters for the flag-sync scan
__device__ unsigned g_cnt[TT];

// ---------------------------------------------------------------------------
__global__ void init_kernel() {
    int i = blockIdx.x * blockDim.x + threadIdx.x;
    if (i < TT) g_cnt[i] = 0u;
}

// ---------------------------------------------------------------------------
__device__ __forceinline__ float sigm(float x) {
    x = fminf(fmaxf(x, -30.f), 30.f);
    return 1.0f / (1.0f + __expf(-x));
}
__device__ __forceinline__ float tanh_e(float x) {
    x = fminf(fmaxf(x, -15.f), 15.f);
    float e = __expf(2.0f * x);
    return (e - 1.0f) / (e + 1.0f);
}

// ---------------------------------------------------------------------------
// Persistent LSTM scan.
// Block blk owns hidden units {2blk, 2blk+1} -> 8 gate columns (i,f,g,o x 2).
// Thread tid = (b<<2)|cg ; cg 0..3 maps to gate (i,f,g,o); each thread
// accumulates 2 gate columns (its gate, both units) for batch b.
// Per step: gates = bias + x_t@Wi_slice + h_{t-1}@Wh_slice ; shfl-exchange the
// 4 gates within the 4-lane group; update c,h; cg0 stores h-pair; flag.
__global__ void __launch_bounds__(NTHR, 1) lstm_scan_kernel(
    const float* __restrict__ x,   // [B,T,D]
    const float* __restrict__ Wi,  // [D,4H]
    const float* __restrict__ Wh,  // [H,4H]
    const float* __restrict__ bias)// [4H]
{
    __shared__ __align__(16) float wh_s[8][260];   // [col][k], padded vs bank conflicts
    __shared__ __align__(16) float wi_s[8][260];
    __shared__ float b_s[8];

    const int tid = threadIdx.x;
    const int blk = blockIdx.x;
    const int u0  = blk * 2;

    // load this block's weight slices (one time)
    for (int idx = tid; idx < 8 * 256; idx += NTHR) {
        int c = idx >> 8, k = idx & 255;
        int gcol = (c >> 1) * HH + u0 + (c & 1);   // c = gate*2 + unit
        wh_s[c][k] = Wh[k * G4 + gcol];
        wi_s[c][k] = Wi[k * G4 + gcol];
    }
    if (tid < 8) b_s[tid] = bias[(tid >> 1) * HH + u0 + (tid & 1)];
    __syncthreads();

    const int b    = tid >> 2;
    const int cg   = tid & 3;
    const int lane = tid & 31;
    const int grp  = lane & ~3;

    const float4* w0i = (const float4*)&wi_s[2*cg  ][0];
    const float4* w1i = (const float4*)&wi_s[2*cg+1][0];
    const float4* w0h = (const float4*)&wh_s[2*cg  ][0];
    const float4* w1h = (const float4*)&wh_s[2*cg+1][0];
    const float bb0 = b_s[2*cg], bb1 = b_s[2*cg+1];

    const float4* xbase = (const float4*)(x + (size_t)b * TT * DD);

    float cs0 = 0.f, cs1 = 0.f;
    const unsigned FULL = 0xffffffffu;

    for (int t = 0; t < TT; ++t) {
        float a0 = bb0, a1 = bb1;

        // --- x_t @ Wi slice : no cross-block dependency, runs before the wait
        const float4* xr = xbase + t * (DD / 4);
        #pragma unroll 8
        for (int kk = 0; kk < DD / 4; ++kk) {
            float4 xv = __ldg(xr + kk);
            float4 wa = w0i[kk];
            float4 wb = w1i[kk];
            a0 = fmaf(xv.x, wa.x, a0); a0 = fmaf(xv.y, wa.y, a0);
            a0 = fmaf(xv.z, wa.z, a0); a0 = fmaf(xv.w, wa.w, a0);
            a1 = fmaf(xv.x, wb.x, a1); a1 = fmaf(xv.y, wb.y, a1);
            a1 = fmaf(xv.z, wb.z, a1); a1 = fmaf(xv.w, wb.w, a1);
        }

        if (t > 0) {
            // --- wait for all blocks to have published h_{t-1}
            if (tid == 0) {
                volatile unsigned* f = &g_cnt[t - 1];
                while (*f < (unsigned)NBLK) { }
                __threadfence();   // acquire: order the spin before h reads
            }
            __syncthreads();

            // --- h_{t-1} @ Wh slice (L2 reads; .cg bypasses L1)
            const float4* hr = (const float4*)&g_h[t - 1][b][0];
            #pragma unroll 8
            for (int kk = 0; kk < HH / 4; ++kk) {
                float4 hv = __ldcg(hr + kk);
                float4 wa = w0h[kk];
                float4 wb = w1h[kk];
                a0 = fmaf(hv.x, wa.x, a0); a0 = fmaf(hv.y, wa.y, a0);
                a0 = fmaf(hv.z, wa.z, a0); a0 = fmaf(hv.w, wa.w, a0);
                a1 = fmaf(hv.x, wb.x, a1); a1 = fmaf(hv.y, wb.y, a1);
                a1 = fmaf(hv.z, wb.z, a1); a1 = fmaf(hv.w, wb.w, a1);
            }
        }

        // --- gather i,f,g,o for both units from the 4-lane group
        float gi0 = __shfl_sync(FULL, a0, grp + 0);
        float gi1 = __shfl_sync(FULL, a1, grp + 0);
        float gf0 = __shfl_sync(FULL, a0, grp + 1);
        float gf1 = __shfl_sync(FULL, a1, grp + 1);
        float gg0 = __shfl_sync(FULL, a0, grp + 2);
        float gg1 = __shfl_sync(FULL, a1, grp + 2);
        float go0 = __shfl_sync(FULL, a0, grp + 3);
        float go1 = __shfl_sync(FULL, a1, grp + 3);

        cs0 = sigm(gf0) * cs0 + sigm(gi0) * tanh_e(gg0);
        cs1 = sigm(gf1) * cs1 + sigm(gi1) * tanh_e(gg1);
        float h0 = sigm(go0) * tanh_e(cs0);
        float h1 = sigm(go1) * tanh_e(cs1);

        if (cg == 0) {
            float2* dst = (float2*)&g_h[t][b][u0];
            *dst = make_float2(h0, h1);
        }
        __syncthreads();
        if (tid == 0) {
            __threadfence();                 // release h stores device-wide
            atomicAdd(&g_cnt[t], 1u);
        }
    }
}

// ---------------------------------------------------------------------------
// block-level reductions (256 threads)
__device__ __forceinline__ float block_sum(float v, volatile float* red) {
    int lane = threadIdx.x & 31, wid = threadIdx.x >> 5;
    #pragma unroll
    for (int o = 16; o; o >>= 1) v += __shfl_down_sync(0xffffffffu, v, o);
    if (lane == 0) red[wid] = v;
    __syncthreads();
    if (threadIdx.x == 0) {
        float s = 0.f;
        #pragma unroll
        for (int i = 0; i < 8; ++i) s += red[i];
        red[0] = s;
    }
    __syncthreads();
    float r = red[0];
    __syncthreads();
    return r;
}
__device__ __forceinline__ float block_max(float v, volatile float* red) {
    int lane = threadIdx.x & 31, wid = threadIdx.x >> 5;
    #pragma unroll
    for (int o = 16; o; o >>= 1) v = fmaxf(v, __shfl_down_sync(0xffffffffu, v, o));
    if (lane == 0) red[wid] = v;
    __syncthreads();
    if (threadIdx.x == 0) {
        float s = red[0];
        #pragma unroll
        for (int i = 1; i < 8; ++i) s = fmaxf(s, red[i]);
        red[0] = s;
    }
    __syncthreads();
    float r = red[0];
    __syncthreads();
    return r;
}

// ---------------------------------------------------------------------------
// Attention + MLP tail. One block per batch element. Exploits:
//   scores_t = scale*((q0 Wk^T)·h_t + q0·bk) ; o0 = (Σ attn_t h_t) Wv + bv
__global__ void __launch_bounds__(NTHR) attn_tail_kernel(
    const float* __restrict__ Wq, const float* __restrict__ bq,
    const float* __restrict__ Wk, const float* __restrict__ bk,
    const float* __restrict__ Wv, const float* __restrict__ bv,
    const float* __restrict__ Wo, const float* __restrict__ bo,
    const float* __restrict__ W1, const float* __restrict__ b1,
    const float* __restrict__ W2, const float* __restrict__ b2,
    float* __restrict__ out)
{
    __shared__ float h0[HH], q0[HH], u[HH], hbar[HH], vb[HH], ob[HH];
    __shared__ float sc[TT];
    __shared__ float z[32];
    __shared__ float red[8];
    __shared__ float qbk_s;

    const int b = blockIdx.x;
    const int tid = threadIdx.x;
    const int lane = tid & 31, wid = tid >> 5;

    h0[tid] = g_h[0][b][tid];
    __syncthreads();

    // q0 = h0 @ Wq + bq  (coalesced over output column = tid)
    {
        float s = bq[tid];
        #pragma unroll 4
        for (int d = 0; d < HH; ++d) s = fmaf(h0[d], Wq[d * HH + tid], s);
        q0[tid] = s;
    }
    __syncthreads();

    // qbk = q0 . bk
    {
        float p = q0[tid] * bk[tid];
        float s = block_sum(p, red);
        if (tid == 0) qbk_s = s;
    }
    __syncthreads();

    // u = q0 @ Wk^T : warp per output row j
    for (int j = wid; j < HH; j += 8) {
        const float* row = Wk + (size_t)j * HH;
        float acc = 0.f;
        #pragma unroll
        for (int d = lane; d < HH; d += 32) acc = fmaf(q0[d], row[d], acc);
        #pragma unroll
        for (int o = 16; o; o >>= 1) acc += __shfl_down_sync(0xffffffffu, acc, o);
        if (lane == 0) u[j] = acc;
    }
    __syncthreads();

    // scores over all t : warp per t
    const float scale = 0.0625f;   // 1/sqrt(256)
    for (int t = wid; t < TT; t += 8) {
        const float* hr = &g_h[t][b][0];
        float acc = 0.f;
        #pragma unroll
        for (int d = lane; d < HH; d += 32) acc = fmaf(u[d], hr[d], acc);
        #pragma unroll
        for (int o = 16; o; o >>= 1) acc += __shfl_down_sync(0xffffffffu, acc, o);
        if (lane == 0) sc[t] = scale * (acc + qbk_s);
    }
    __syncthreads();

    // softmax over T=512 (2 elements / thread)
    {
        float s0 = sc[tid], s1 = sc[tid + 256];
        float M = block_max(fmaxf(s0, s1), red);
        float e0 = __expf(s0 - M), e1 = __expf(s1 - M);
        float S = block_sum(e0 + e1, red);
        float inv = 1.f / S;
        sc[tid] = e0 * inv;
        sc[tid + 256] = e1 * inv;
    }
    __syncthreads();

    // hbar[d] = sum_t attn[t] * h[t][b][d]
    {
        float acc = 0.f;
        #pragma unroll 4
        for (int t = 0; t < TT; ++t) acc = fmaf(sc[t], g_h[t][b][tid], acc);
        hbar[tid] = acc;
    }
    __syncthreads();

    // vb = hbar @ Wv + bv
    {
        float s = bv[tid];
        #pragma unroll 4
        for (int d = 0; d < HH; ++d) s = fmaf(hbar[d], Wv[d * HH + tid], s);
        vb[tid] = s;
    }
    __syncthreads();

    // ob = vb @ Wo + bo
    {
        float s = bo[tid];
        #pragma unroll 4
        for (int d = 0; d < HH; ++d) s = fmaf(vb[d], Wo[d * HH + tid], s);
        ob[tid] = s;
    }
    __syncthreads();

    // z = relu(ob @ W1 + b1)   [32]
    if (tid < 32) {
        float s = b1[tid];
        #pragma unroll 4
        for (int d = 0; d < HH; ++d) s = fmaf(ob[d], W1[d * 32 + tid], s);
        z[tid] = fmaxf(s, 0.f);
    }
    __syncthreads();

    // out = z @ W2 + b2   [3]
    if (tid < 3) {
        float s = b2[tid];
        #pragma unroll
        for (int d = 0; d < 32; ++d) s = fmaf(z[d], W2[d * 3 + tid], s);
        out[b * 3 + tid] = s;
    }
}

// ---------------------------------------------------------------------------
extern "C" void kernel_launch(void* const* d_in, const int* in_sizes, int n_in,
                              void* d_out, int out_size) {
    const float* x  = (const float*)d_in[0];
    const float* Wi = (const float*)d_in[1];
    const float* Wh = (const float*)d_in[2];
    const float* bg = (const float*)d_in[3];
    const float* Wq = (const float*)d_in[4];
    const float* bq = (const float*)d_in[5];
    const float* Wk = (const float*)d_in[6];
    const float* bk = (const float*)d_in[7];
    const float* Wv = (const float*)d_in[8];
    const float* bv = (const float*)d_in[9];
    const float* Wo = (const float*)d_in[10];
    const float* bo = (const float*)d_in[11];
    const float* W1 = (const float*)d_in[12];
    const float* b1 = (const float*)d_in[13];
    const float* W2 = (const float*)d_in[14];
    const float* b2 = (const float*)d_in[15];
    float* out = (float*)d_out;

    init_kernel<<<1, TT>>>();
    lstm_scan_kernel<<<NBLK, NTHR>>>(x, Wi, Wh, bg);
    attn_tail_kernel<<<BB, NTHR>>>(Wq, bq, Wk, bk, Wv, bv, Wo, bo,
                                   W1, b1, W2, b2, out);
}